// round 16
// baseline (speedup 1.0000x reference)
#include <cuda_runtime.h>
#include <cuda_fp16.h>
#include <cstdint>

#define NN 50000
#define EE 800000
#define RR 3
#define DD 128
#define HH 4
#define MSEG (RR * NN)            // 150000 segments, keyed seg = dst*RR + r
#define SCAN_BLK 1024
#define NSB ((MSEG + SCAN_BLK - 1) / SCAN_BLK)   // 147

// ---------------- scratch (device globals) --------------------------------------
__device__ __align__(16) __half g_hh[(size_t)RR * NN * DD]; // fp16 features
__device__ float g_asrc[RR * NN * HH];
__device__ float g_adst[RR * NN * HH];
__device__ float g_gw[RR];
__device__ float g_biasf[DD];
__device__ int   g_cnt[MSEG];
__device__ int   g_off[MSEG];
__device__ int   g_cur[MSEG];
__device__ int   g_bsum[256];
__device__ int   g_esrc[RR * EE];

// ---------------- packed fp32x2 + cp.async helpers -------------------------------
#define PACK_DUP(d, f) asm("mov.b64 %0, {%1, %2};" : "=l"(d) : "f"(f), "f"(f))
#define FMA2(d, a, b, c) \
    asm("fma.rn.f32x2 %0, %1, %2, %3;" : "=l"(d) : "l"(a), "l"(b), "l"(c))
#define CP16(dst, src, nbytes) \
    asm volatile("cp.async.ca.shared.global [%0], [%1], 16, %2;" \
                 :: "r"(dst), "l"(src), "r"(nbytes))
#define CP_COMMIT() asm volatile("cp.async.commit_group;" ::: "memory")
#define CP_WAIT1()  asm volatile("cp.async.wait_group 1;" ::: "memory")
#define CP_WAIT0()  asm volatile("cp.async.wait_group 0;" ::: "memory")

__device__ __forceinline__ uint32_t smem_u32(const void* p) {
    uint32_t a;
    asm("{ .reg .u64 t; cvta.to.shared.u64 t, %1; cvt.u32.u64 %0, t; }" : "=r"(a) : "l"(p));
    return a;
}

// ---------------- K0: gate softmax + fused bias ---------------------------------
__global__ void k_prep(const float* __restrict__ gate,
                       const float* __restrict__ bias,
                       float* __restrict__ out_gw) {
    __shared__ float gw[RR];
    int d = threadIdx.x;  // 128
    if (d == 0) {
        float m = gate[0];
        for (int r = 1; r < RR; r++) m = fmaxf(m, gate[r]);
        float e[RR], s = 0.f;
        for (int r = 0; r < RR; r++) { e[r] = expf(gate[r] - m); s += e[r]; }
        for (int r = 0; r < RR; r++) {
            gw[r] = e[r] / s;
            g_gw[r] = gw[r];
            out_gw[r] = gw[r];
        }
    }
    __syncthreads();
    float b = 0.f;
    for (int r = 0; r < RR; r++) b += gw[r] * bias[r * DD + d];
    g_biasf[d] = b;
}

// ---------------- K1: zero degree counts ----------------------------------------
__global__ void k_init() {
    int i = blockIdx.x * blockDim.x + threadIdx.x;
    if (i < MSEG / 4) ((int4*)g_cnt)[i] = make_int4(0, 0, 0, 0);
}

// ---------------- K2: GEMM (cp.async double-buffered) + fused alpha epilogue -----
#define BM 128
#define BK 32
#define OX(buf) ((buf) * 16384)             // Xs[buf][128 rows][128B, swizzled]
#define OW(buf) (32768 + (buf) * 16384)     // Ws[buf][32 rows][512B]
#define OAS 65536
#define OAD (65536 + 512)
#define GEMM_SMEM (65536 + 1024)

__global__ void __launch_bounds__(256, 2)
k_gemm(const float* __restrict__ x, const float* __restrict__ W,
       const float* __restrict__ att_src, const float* __restrict__ att_dst) {
    extern __shared__ char sm[];
    const uint32_t sb = smem_u32(sm);
    float* as_s = (float*)(sm + OAS);
    float* ad_s = (float*)(sm + OAD);

    const int r = blockIdx.y;
    const int row0 = blockIdx.x * BM;
    const int tid = threadIdx.x;
    const int tx = tid & 15;
    const int ty = tid >> 4;
    const float* Wr = W + (size_t)r * DD * DD;

    if (tid < DD) {
        as_s[tid] = __ldg(&att_src[r * DD + tid]);
        ad_s[tid] = __ldg(&att_dst[r * DD + tid]);
    }

    const int lrow = tid >> 1;
    const int lgrow = row0 + lrow;
    const int xbytes = (lgrow < NN) ? 16 : 0;
    const char* xsrc = (const char*)(x + (size_t)(lgrow < NN ? lgrow : 0) * DD)
                       + (tid & 1) * 64;
    const uint32_t xsw = ((uint32_t)(lrow >> 3) & 7) << 4;
    const uint32_t xdst_row = sb + lrow * 128 + 0;

#define LOAD_STAGE(k0, buf)                                                        \
    do {                                                                           \
        _Pragma("unroll")                                                          \
        for (int q = 0; q < 4; q++) {                                              \
            uint32_t off = (uint32_t)((tid & 1) * 64 + q * 16);                    \
            CP16(xdst_row + OX(buf) + (off ^ xsw), xsrc + (k0) * BK * 4 + q * 16,  \
                 xbytes);                                                          \
        }                                                                          \
        const char* wsrc = (const char*)(Wr + (size_t)(k0) * BK * DD);             \
        _Pragma("unroll")                                                          \
        for (int q = 0; q < 4; q++) {                                              \
            uint32_t c16 = (uint32_t)((q * 256 + tid) * 16);                       \
            CP16(sb + OW(buf) + c16, wsrc + c16, 16);                              \
        }                                                                          \
    } while (0)

    unsigned long long acc[8][4];   // [row p][col-pair cp]
#pragma unroll
    for (int p = 0; p < 8; p++)
#pragma unroll
        for (int cp = 0; cp < 4; cp++) acc[p][cp] = 0ULL;

    LOAD_STAGE(0, 0); CP_COMMIT();
    LOAD_STAGE(1, 1); CP_COMMIT();

    const uint32_t aswz = ((uint32_t)ty & 7) << 4;

#pragma unroll
    for (int t = 0; t < 4; t++) {
        if (t < 3) { CP_WAIT1(); } else { CP_WAIT0(); }
        __syncthreads();

        const int buf = t & 1;
        const char* xb = sm + OX(buf);
        const char* wb = sm + OW(buf);

#pragma unroll
        for (int kk4 = 0; kk4 < 8; kk4++) {
            float4 af[8];
            uint32_t coff = ((uint32_t)(kk4 * 16)) ^ aswz;
#pragma unroll
            for (int p = 0; p < 8; p++)
                af[p] = *(const float4*)(xb + (ty * 8 + p) * 128 + coff);
#pragma unroll
            for (int kki = 0; kki < 4; kki++) {
                int kk = kk4 * 4 + kki;
                ulonglong2 b01 = *(const ulonglong2*)(wb + kk * 512 + tx * 32);
                ulonglong2 b23 = *(const ulonglong2*)(wb + kk * 512 + tx * 32 + 16);
#pragma unroll
                for (int p = 0; p < 8; p++) {
                    float a = (kki == 0) ? af[p].x : (kki == 1) ? af[p].y
                              : (kki == 2) ? af[p].z : af[p].w;
                    unsigned long long aa;
                    PACK_DUP(aa, a);
                    FMA2(acc[p][0], aa, b01.x, acc[p][0]);
                    FMA2(acc[p][1], aa, b01.y, acc[p][1]);
                    FMA2(acc[p][2], aa, b23.x, acc[p][2]);
                    FMA2(acc[p][3], aa, b23.y, acc[p][3]);
                }
            }
        }
        __syncthreads();
        if (t + 2 <= 3) { LOAD_STAGE(t + 2, buf); CP_COMMIT(); }
    }
#undef LOAD_STAGE

    // ---- epilogue: fp16 store + fused attention-logit dots ----------------------
    const int head = tx >> 2;
    float asv[8], adv[8];
#pragma unroll
    for (int j = 0; j < 8; j++) {
        asv[j] = as_s[tx * 8 + j];
        adv[j] = ad_s[tx * 8 + j];
    }

#pragma unroll
    for (int p = 0; p < 8; p++) {
        int grow = row0 + ty * 8 + p;
        float c[8];
#pragma unroll
        for (int cp = 0; cp < 4; cp++) {
            float2 v = *(float2*)&acc[p][cp];
            c[2 * cp] = v.x;
            c[2 * cp + 1] = v.y;
        }
        float ps = 0.f, pd = 0.f;
#pragma unroll
        for (int j = 0; j < 8; j++) {
            ps += c[j] * asv[j];
            pd += c[j] * adv[j];
        }
#pragma unroll
        for (int o = 1; o <= 2; o <<= 1) {
            ps += __shfl_xor_sync(0xffffffffu, ps, o);
            pd += __shfl_xor_sync(0xffffffffu, pd, o);
        }
        __half2 oh[4];
#pragma unroll
        for (int j = 0; j < 4; j++)
            oh[j] = __floats2half2_rn(c[2 * j], c[2 * j + 1]);
        if (grow < NN) {
            *(uint4*)&g_hh[((size_t)r * NN + grow) * DD + tx * 8] = *(uint4*)oh;
            if ((tx & 3) == 0) {
                g_asrc[((size_t)r * NN + grow) * HH + head] = ps;
                g_adst[((size_t)r * NN + grow) * HH + head] = pd;
            }
        }
    }
}

// ---------------- K4a: degree histogram (seg = dst*RR + r) -----------------------
__global__ void k_hist(const int* __restrict__ ei) {
    int e = blockIdx.x * blockDim.x + threadIdx.x;
    int r = blockIdx.y;
    if (e >= EE) return;
    int dst = __ldg(&ei[r * 2 * EE + EE + e]);
    atomicAdd(&g_cnt[dst * RR + r], 1);
}

// ---------------- K4b: scan stage 1 — per-block sums ------------------------------
__global__ void k_scan_a() {
    __shared__ int ws[8];
    int tid = threadIdx.x;
    int base = blockIdx.x * SCAN_BLK + tid * 4;
    int s = 0;
#pragma unroll
    for (int k = 0; k < 4; k++) {
        int idx = base + k;
        if (idx < MSEG) s += g_cnt[idx];
    }
#pragma unroll
    for (int o = 16; o >= 1; o >>= 1) s += __shfl_xor_sync(0xffffffffu, s, o);
    if ((tid & 31) == 0) ws[tid >> 5] = s;
    __syncthreads();
    if (tid == 0) {
        int t = 0;
        for (int i = 0; i < 8; i++) t += ws[i];
        g_bsum[blockIdx.x] = t;
    }
}

// ---------------- K4c: scan stage 2 — offsets (block prefix in-kernel) ------------
__global__ void k_scan_c() {
    __shared__ int ws[8];
    __shared__ int blk_base;
    int tid = threadIdx.x;
    int lane = tid & 31, warp = tid >> 5;

    {
        int s = 0;
        for (int i = tid; i < blockIdx.x; i += 256) s += g_bsum[i];
#pragma unroll
        for (int o = 16; o >= 1; o >>= 1) s += __shfl_xor_sync(0xffffffffu, s, o);
        if (lane == 0) ws[warp] = s;
        __syncthreads();
        if (tid == 0) {
            int t = 0;
            for (int i = 0; i < 8; i++) t += ws[i];
            blk_base = t;
        }
        __syncthreads();
    }

    int base = blockIdx.x * SCAN_BLK + tid * 4;
    int c[4];
#pragma unroll
    for (int k = 0; k < 4; k++) {
        int idx = base + k;
        c[k] = (idx < MSEG) ? g_cnt[idx] : 0;
    }
    int t = c[0] + c[1] + c[2] + c[3];
    int inc = t;
#pragma unroll
    for (int o = 1; o < 32; o <<= 1) {
        int v = __shfl_up_sync(0xffffffffu, inc, o);
        if (lane >= o) inc += v;
    }
    if (lane == 31) ws[warp] = inc;
    __syncthreads();
    if (tid == 0) {
        int run = 0;
        for (int i = 0; i < 8; i++) { int v = ws[i]; ws[i] = run; run += v; }
    }
    __syncthreads();
    int ex = inc - t + ws[warp] + blk_base;
#pragma unroll
    for (int k = 0; k < 4; k++) {
        int idx = base + k;
        if (idx < MSEG) { g_off[idx] = ex; g_cur[idx] = ex; }
        ex += c[k];
    }
}

// ---------------- K4e: scatter edges into CSR ------------------------------------
__global__ void k_scatter(const int* __restrict__ ei) {
    int e = blockIdx.x * blockDim.x + threadIdx.x;
    int r = blockIdx.y;
    if (e >= EE) return;
    int src = __ldg(&ei[r * 2 * EE + e]);
    int dst = __ldg(&ei[r * 2 * EE + EE + e]);
    int pos = atomicAdd(&g_cur[dst * RR + r], 1);
    g_esrc[pos] = src;
}

// ---------------- K5: fused aggregation + residual + LayerNorm (warp per dst) ----
// Clamped 8-wide batches: ALL loads issued in parallel regardless of degree;
// accumulation predicated on in-range. A degree-5 segment = 1 latency round.
__global__ void __launch_bounds__(256)
k_agg(const float* __restrict__ x,
      const float* __restrict__ gamma,
      const float* __restrict__ beta,
      float* __restrict__ out) {
    int dst = (blockIdx.x * blockDim.x + threadIdx.x) >> 5;
    int lane = threadIdx.x & 31;
    if (dst >= NN) return;
    int head = lane >> 3;
    int c4 = lane * 4;

    float4 xv = __ldg((const float4*)&x[(size_t)dst * DD + c4]);
    float4 bf = *(const float4*)&g_biasf[c4];
    float4 acc = make_float4(xv.x + bf.x, xv.y + bf.y, xv.z + bf.z, xv.w + bf.w);

#pragma unroll
    for (int r = 0; r < RR; r++) {
        int seg = dst * RR + r;
        int beg = g_off[seg];
        int end = g_cur[seg];
        if (beg == end) continue;

        float adv = g_adst[((size_t)r * NN + dst) * HH + head];
        const __half* hr = g_hh + (size_t)r * NN * DD;
        const float* ar = g_asrc + (size_t)r * NN * HH;

        float denom = 0.f;
        float4 part = make_float4(0.f, 0.f, 0.f, 0.f);

        for (int i = beg; i < end; i += 8) {
            int sI[8];
#pragma unroll
            for (int q = 0; q < 8; q++) {
                int idx = i + q;
                sI[q] = __ldg(&g_esrc[idx < end ? idx : end - 1]);
            }
            float aV[8];
#pragma unroll
            for (int q = 0; q < 8; q++) aV[q] = __ldg(&ar[sI[q] * HH + head]);
            uint2 hV[8];
#pragma unroll
            for (int q = 0; q < 8; q++)
                hV[q] = __ldg((const uint2*)&hr[(size_t)sI[q] * DD + c4]);
#pragma unroll
            for (int q = 0; q < 8; q++) {
                if (i + q < end) {
                    float v = aV[q] + adv;
                    v = v >= 0.f ? v : 0.2f * v;
                    float w = __expf(v);
                    denom += w;
                    float2 f0 = __half22float2(*(__half2*)&hV[q].x);
                    float2 f1 = __half22float2(*(__half2*)&hV[q].y);
                    part.x += w * f0.x; part.y += w * f0.y;
                    part.z += w * f1.x; part.w += w * f1.y;
                }
            }
        }
        float scale = g_gw[r] / (denom + 1e-16f);
        acc.x += scale * part.x; acc.y += scale * part.y;
        acc.z += scale * part.z; acc.w += scale * part.w;
    }

    float s = acc.x + acc.y + acc.z + acc.w;
    float q = acc.x * acc.x + acc.y * acc.y + acc.z * acc.z + acc.w * acc.w;
#pragma unroll
    for (int o = 16; o >= 1; o >>= 1) {
        s += __shfl_xor_sync(0xffffffffu, s, o);
        q += __shfl_xor_sync(0xffffffffu, q, o);
    }
    float mu = s * (1.f / DD);
    float var = q * (1.f / DD) - mu * mu;
    float rstd = rsqrtf(var + 1e-5f);
    float4 g = __ldg((const float4*)&gamma[c4]);
    float4 b = __ldg((const float4*)&beta[c4]);
    float4 o4;
    o4.x = (acc.x - mu) * rstd * g.x + b.x;
    o4.y = (acc.y - mu) * rstd * g.y + b.y;
    o4.z = (acc.z - mu) * rstd * g.z + b.z;
    o4.w = (acc.w - mu) * rstd * g.w + b.w;
    *(float4*)&out[(size_t)dst * DD + c4] = o4;
}

// ---------------- launch ------------------------------------------------------------
extern "C" void kernel_launch(void* const* d_in, const int* in_sizes, int n_in,
                              void* d_out, int out_size) {
    const float* x       = (const float*)d_in[0];
    const int*   ei      = (const int*)d_in[1];
    const float* W       = (const float*)d_in[3];
    const float* att_src = (const float*)d_in[4];
    const float* att_dst = (const float*)d_in[5];
    const float* bias    = (const float*)d_in[6];
    const float* gate    = (const float*)d_in[7];
    const float* gamma   = (const float*)d_in[8];
    const float* beta    = (const float*)d_in[9];
    float* out = (float*)d_out;

    static cudaStream_t s2 = nullptr;
    static cudaEvent_t evFork = nullptr, evJoin = nullptr;
    if (s2 == nullptr) {
        cudaStreamCreateWithFlags(&s2, cudaStreamNonBlocking);
        cudaEventCreateWithFlags(&evFork, cudaEventDisableTiming);
        cudaEventCreateWithFlags(&evJoin, cudaEventDisableTiming);
        cudaFuncSetAttribute(k_gemm, cudaFuncAttributeMaxDynamicSharedMemorySize,
                             GEMM_SMEM);
    }

    // fork: CSR-build + prep branch runs concurrently with the GEMM branch
    cudaEventRecord(evFork, 0);
    cudaStreamWaitEvent(s2, evFork, 0);

    // ---- branch B (stream s2): prep + CSR build ----
    k_prep<<<1, DD, 0, s2>>>(gate, bias, out + (out_size - RR));
    k_init<<<(MSEG / 4 + 255) / 256, 256, 0, s2>>>();
    dim3 gh((EE + 511) / 512, RR);
    k_hist<<<gh, 512, 0, s2>>>(ei);
    k_scan_a<<<NSB, 256, 0, s2>>>();
    k_scan_c<<<NSB, 256, 0, s2>>>();
    k_scatter<<<gh, 512, 0, s2>>>(ei);
    cudaEventRecord(evJoin, s2);

    // ---- branch A (default stream): GEMM + fused alpha ----
    dim3 gg((NN + BM - 1) / BM, RR);
    k_gemm<<<gg, 256, GEMM_SMEM>>>(x, W, att_src, att_dst);

    // join, then fused aggregation + residual + LayerNorm
    cudaStreamWaitEvent(0, evJoin, 0);
    k_agg<<<(NN * 32 + 255) / 256, 256>>>(x, gamma, beta, out);
}

// round 17
// speedup vs baseline: 1.1771x; 1.1771x over previous
#include <cuda_runtime.h>
#include <cuda_fp16.h>
#include <cstdint>

#define NN 50000
#define EE 800000
#define RR 3
#define DD 128
#define HH 4
#define MSEG (RR * NN)            // 150000 segments, keyed seg = dst*RR + r
#define SCAN_BLK 1024
#define NSB ((MSEG + SCAN_BLK - 1) / SCAN_BLK)   // 147

// ---------------- scratch (device globals) --------------------------------------
__device__ __align__(16) __half g_hh[(size_t)RR * NN * DD]; // fp16 features
__device__ float g_asrc[RR * NN * HH];
__device__ float g_adst[RR * NN * HH];
__device__ float g_gw[RR];
__device__ float g_biasf[DD];
__device__ int   g_cnt[MSEG];
__device__ int   g_off[MSEG];
__device__ int   g_cur[MSEG];
__device__ int   g_bsum[256];
__device__ int   g_esrc[RR * EE];

// ---------------- packed fp32x2 + cp.async helpers -------------------------------
#define PACK_DUP(d, f) asm("mov.b64 %0, {%1, %2};" : "=l"(d) : "f"(f), "f"(f))
#define FMA2(d, a, b, c) \
    asm("fma.rn.f32x2 %0, %1, %2, %3;" : "=l"(d) : "l"(a), "l"(b), "l"(c))
#define CP16(dst, src, nbytes) \
    asm volatile("cp.async.ca.shared.global [%0], [%1], 16, %2;" \
                 :: "r"(dst), "l"(src), "r"(nbytes))
#define CP_COMMIT() asm volatile("cp.async.commit_group;" ::: "memory")
#define CP_WAIT1()  asm volatile("cp.async.wait_group 1;" ::: "memory")
#define CP_WAIT0()  asm volatile("cp.async.wait_group 0;" ::: "memory")

__device__ __forceinline__ uint32_t smem_u32(const void* p) {
    uint32_t a;
    asm("{ .reg .u64 t; cvta.to.shared.u64 t, %1; cvt.u32.u64 %0, t; }" : "=r"(a) : "l"(p));
    return a;
}

// ---------------- K0: gate softmax + fused bias ---------------------------------
__global__ void k_prep(const float* __restrict__ gate,
                       const float* __restrict__ bias,
                       float* __restrict__ out_gw) {
    __shared__ float gw[RR];
    int d = threadIdx.x;  // 128
    if (d == 0) {
        float m = gate[0];
        for (int r = 1; r < RR; r++) m = fmaxf(m, gate[r]);
        float e[RR], s = 0.f;
        for (int r = 0; r < RR; r++) { e[r] = expf(gate[r] - m); s += e[r]; }
        for (int r = 0; r < RR; r++) {
            gw[r] = e[r] / s;
            g_gw[r] = gw[r];
            out_gw[r] = gw[r];
        }
    }
    __syncthreads();
    float b = 0.f;
    for (int r = 0; r < RR; r++) b += gw[r] * bias[r * DD + d];
    g_biasf[d] = b;
}

// ---------------- K1: zero degree counts ----------------------------------------
__global__ void k_init() {
    int i = blockIdx.x * blockDim.x + threadIdx.x;
    if (i < MSEG / 4) ((int4*)g_cnt)[i] = make_int4(0, 0, 0, 0);
}

// ---------------- K2: GEMM (cp.async double-buffered) + fused alpha epilogue -----
#define BM 128
#define BK 32
#define OX(buf) ((buf) * 16384)             // Xs[buf][128 rows][128B, swizzled]
#define OW(buf) (32768 + (buf) * 16384)     // Ws[buf][32 rows][512B]
#define OAS 65536
#define OAD (65536 + 512)
#define GEMM_SMEM (65536 + 1024)

__global__ void __launch_bounds__(256, 2)
k_gemm(const float* __restrict__ x, const float* __restrict__ W,
       const float* __restrict__ att_src, const float* __restrict__ att_dst) {
    extern __shared__ char sm[];
    const uint32_t sb = smem_u32(sm);
    float* as_s = (float*)(sm + OAS);
    float* ad_s = (float*)(sm + OAD);

    const int r = blockIdx.y;
    const int row0 = blockIdx.x * BM;
    const int tid = threadIdx.x;
    const int tx = tid & 15;
    const int ty = tid >> 4;
    const float* Wr = W + (size_t)r * DD * DD;

    if (tid < DD) {
        as_s[tid] = __ldg(&att_src[r * DD + tid]);
        ad_s[tid] = __ldg(&att_dst[r * DD + tid]);
    }

    const int lrow = tid >> 1;
    const int lgrow = row0 + lrow;
    const int xbytes = (lgrow < NN) ? 16 : 0;
    const char* xsrc = (const char*)(x + (size_t)(lgrow < NN ? lgrow : 0) * DD)
                       + (tid & 1) * 64;
    const uint32_t xsw = ((uint32_t)(lrow >> 3) & 7) << 4;
    const uint32_t xdst_row = sb + lrow * 128 + 0;

#define LOAD_STAGE(k0, buf)                                                        \
    do {                                                                           \
        _Pragma("unroll")                                                          \
        for (int q = 0; q < 4; q++) {                                              \
            uint32_t off = (uint32_t)((tid & 1) * 64 + q * 16);                    \
            CP16(xdst_row + OX(buf) + (off ^ xsw), xsrc + (k0) * BK * 4 + q * 16,  \
                 xbytes);                                                          \
        }                                                                          \
        const char* wsrc = (const char*)(Wr + (size_t)(k0) * BK * DD);             \
        _Pragma("unroll")                                                          \
        for (int q = 0; q < 4; q++) {                                              \
            uint32_t c16 = (uint32_t)((q * 256 + tid) * 16);                       \
            CP16(sb + OW(buf) + c16, wsrc + c16, 16);                              \
        }                                                                          \
    } while (0)

    unsigned long long acc[8][4];   // [row p][col-pair cp]
#pragma unroll
    for (int p = 0; p < 8; p++)
#pragma unroll
        for (int cp = 0; cp < 4; cp++) acc[p][cp] = 0ULL;

    LOAD_STAGE(0, 0); CP_COMMIT();
    LOAD_STAGE(1, 1); CP_COMMIT();

    const uint32_t aswz = ((uint32_t)ty & 7) << 4;

#pragma unroll
    for (int t = 0; t < 4; t++) {
        if (t < 3) { CP_WAIT1(); } else { CP_WAIT0(); }
        __syncthreads();

        const int buf = t & 1;
        const char* xb = sm + OX(buf);
        const char* wb = sm + OW(buf);

#pragma unroll
        for (int kk4 = 0; kk4 < 8; kk4++) {
            float4 af[8];
            uint32_t coff = ((uint32_t)(kk4 * 16)) ^ aswz;
#pragma unroll
            for (int p = 0; p < 8; p++)
                af[p] = *(const float4*)(xb + (ty * 8 + p) * 128 + coff);
#pragma unroll
            for (int kki = 0; kki < 4; kki++) {
                int kk = kk4 * 4 + kki;
                ulonglong2 b01 = *(const ulonglong2*)(wb + kk * 512 + tx * 32);
                ulonglong2 b23 = *(const ulonglong2*)(wb + kk * 512 + tx * 32 + 16);
#pragma unroll
                for (int p = 0; p < 8; p++) {
                    float a = (kki == 0) ? af[p].x : (kki == 1) ? af[p].y
                              : (kki == 2) ? af[p].z : af[p].w;
                    unsigned long long aa;
                    PACK_DUP(aa, a);
                    FMA2(acc[p][0], aa, b01.x, acc[p][0]);
                    FMA2(acc[p][1], aa, b01.y, acc[p][1]);
                    FMA2(acc[p][2], aa, b23.x, acc[p][2]);
                    FMA2(acc[p][3], aa, b23.y, acc[p][3]);
                }
            }
        }
        __syncthreads();
        if (t + 2 <= 3) { LOAD_STAGE(t + 2, buf); CP_COMMIT(); }
    }
#undef LOAD_STAGE

    // ---- epilogue: fp16 store + fused attention-logit dots ----------------------
    const int head = tx >> 2;
    float asv[8], adv[8];
#pragma unroll
    for (int j = 0; j < 8; j++) {
        asv[j] = as_s[tx * 8 + j];
        adv[j] = ad_s[tx * 8 + j];
    }

#pragma unroll
    for (int p = 0; p < 8; p++) {
        int grow = row0 + ty * 8 + p;
        float c[8];
#pragma unroll
        for (int cp = 0; cp < 4; cp++) {
            float2 v = *(float2*)&acc[p][cp];
            c[2 * cp] = v.x;
            c[2 * cp + 1] = v.y;
        }
        float ps = 0.f, pd = 0.f;
#pragma unroll
        for (int j = 0; j < 8; j++) {
            ps += c[j] * asv[j];
            pd += c[j] * adv[j];
        }
#pragma unroll
        for (int o = 1; o <= 2; o <<= 1) {
            ps += __shfl_xor_sync(0xffffffffu, ps, o);
            pd += __shfl_xor_sync(0xffffffffu, pd, o);
        }
        __half2 oh[4];
#pragma unroll
        for (int j = 0; j < 4; j++)
            oh[j] = __floats2half2_rn(c[2 * j], c[2 * j + 1]);
        if (grow < NN) {
            *(uint4*)&g_hh[((size_t)r * NN + grow) * DD + tx * 8] = *(uint4*)oh;
            if ((tx & 3) == 0) {
                g_asrc[((size_t)r * NN + grow) * HH + head] = ps;
                g_adst[((size_t)r * NN + grow) * HH + head] = pd;
            }
        }
    }
}

// ---------------- K4a: degree histogram (seg = dst*RR + r) -----------------------
__global__ void k_hist(const int* __restrict__ ei) {
    int e = blockIdx.x * blockDim.x + threadIdx.x;
    int r = blockIdx.y;
    if (e >= EE) return;
    int dst = __ldg(&ei[r * 2 * EE + EE + e]);
    atomicAdd(&g_cnt[dst * RR + r], 1);
}

// ---------------- K4b: scan stage 1 — per-block sums ------------------------------
__global__ void k_scan_a() {
    __shared__ int ws[8];
    int tid = threadIdx.x;
    int base = blockIdx.x * SCAN_BLK + tid * 4;
    int s = 0;
#pragma unroll
    for (int k = 0; k < 4; k++) {
        int idx = base + k;
        if (idx < MSEG) s += g_cnt[idx];
    }
#pragma unroll
    for (int o = 16; o >= 1; o >>= 1) s += __shfl_xor_sync(0xffffffffu, s, o);
    if ((tid & 31) == 0) ws[tid >> 5] = s;
    __syncthreads();
    if (tid == 0) {
        int t = 0;
        for (int i = 0; i < 8; i++) t += ws[i];
        g_bsum[blockIdx.x] = t;
    }
}

// ---------------- K4c: scan stage 2 — offsets (block prefix in-kernel) ------------
__global__ void k_scan_c() {
    __shared__ int ws[8];
    __shared__ int blk_base;
    int tid = threadIdx.x;
    int lane = tid & 31, warp = tid >> 5;

    {
        int s = 0;
        for (int i = tid; i < blockIdx.x; i += 256) s += g_bsum[i];
#pragma unroll
        for (int o = 16; o >= 1; o >>= 1) s += __shfl_xor_sync(0xffffffffu, s, o);
        if (lane == 0) ws[warp] = s;
        __syncthreads();
        if (tid == 0) {
            int t = 0;
            for (int i = 0; i < 8; i++) t += ws[i];
            blk_base = t;
        }
        __syncthreads();
    }

    int base = blockIdx.x * SCAN_BLK + tid * 4;
    int c[4];
#pragma unroll
    for (int k = 0; k < 4; k++) {
        int idx = base + k;
        c[k] = (idx < MSEG) ? g_cnt[idx] : 0;
    }
    int t = c[0] + c[1] + c[2] + c[3];
    int inc = t;
#pragma unroll
    for (int o = 1; o < 32; o <<= 1) {
        int v = __shfl_up_sync(0xffffffffu, inc, o);
        if (lane >= o) inc += v;
    }
    if (lane == 31) ws[warp] = inc;
    __syncthreads();
    if (tid == 0) {
        int run = 0;
        for (int i = 0; i < 8; i++) { int v = ws[i]; ws[i] = run; run += v; }
    }
    __syncthreads();
    int ex = inc - t + ws[warp] + blk_base;
#pragma unroll
    for (int k = 0; k < 4; k++) {
        int idx = base + k;
        if (idx < MSEG) { g_off[idx] = ex; g_cur[idx] = ex; }
        ex += c[k];
    }
}

// ---------------- K4e: scatter edges into CSR ------------------------------------
__global__ void k_scatter(const int* __restrict__ ei) {
    int e = blockIdx.x * blockDim.x + threadIdx.x;
    int r = blockIdx.y;
    if (e >= EE) return;
    int src = __ldg(&ei[r * 2 * EE + e]);
    int dst = __ldg(&ei[r * 2 * EE + EE + e]);
    int pos = atomicAdd(&g_cur[dst * RR + r], 1);
    g_esrc[pos] = src;
}

// ---------------- K5: fused aggregation + residual + LayerNorm (warp per dst) ----
__global__ void __launch_bounds__(256)
k_agg(const float* __restrict__ x,
      const float* __restrict__ gamma,
      const float* __restrict__ beta,
      float* __restrict__ out) {
    int dst = (blockIdx.x * blockDim.x + threadIdx.x) >> 5;
    int lane = threadIdx.x & 31;
    if (dst >= NN) return;
    int head = lane >> 3;
    int c4 = lane * 4;

    float4 xv = __ldg((const float4*)&x[(size_t)dst * DD + c4]);
    float4 bf = *(const float4*)&g_biasf[c4];
    float4 acc = make_float4(xv.x + bf.x, xv.y + bf.y, xv.z + bf.z, xv.w + bf.w);

#pragma unroll
    for (int r = 0; r < RR; r++) {
        int seg = dst * RR + r;
        int beg = g_off[seg];
        int end = g_cur[seg];
        if (beg == end) continue;

        float adv = g_adst[((size_t)r * NN + dst) * HH + head];
        const __half* hr = g_hh + (size_t)r * NN * DD;
        const float* ar = g_asrc + (size_t)r * NN * HH;

        float denom = 0.f;
        float4 part = make_float4(0.f, 0.f, 0.f, 0.f);

        int i = beg;
        for (; i + 8 <= end; i += 8) {
            int sI[8];
#pragma unroll
            for (int q = 0; q < 8; q++) sI[q] = __ldg(&g_esrc[i + q]);
            float aV[8];
            uint2 hV[8];
#pragma unroll
            for (int q = 0; q < 8; q++) aV[q] = __ldg(&ar[sI[q] * HH + head]);
#pragma unroll
            for (int q = 0; q < 8; q++)
                hV[q] = __ldg((const uint2*)&hr[(size_t)sI[q] * DD + c4]);
#pragma unroll
            for (int q = 0; q < 8; q++) {
                float v = aV[q] + adv;
                v = v >= 0.f ? v : 0.2f * v;
                float w = __expf(v);
                denom += w;
                float2 f0 = __half22float2(*(__half2*)&hV[q].x);
                float2 f1 = __half22float2(*(__half2*)&hV[q].y);
                part.x += w * f0.x; part.y += w * f0.y;
                part.z += w * f1.x; part.w += w * f1.y;
            }
        }
        for (; i < end; i++) {
            int src = __ldg(&g_esrc[i]);
            float asv = __ldg(&ar[src * HH + head]);
            float v = asv + adv;
            v = v >= 0.f ? v : 0.2f * v;
            float w = __expf(v);
            denom += w;
            uint2 hv = __ldg((const uint2*)&hr[(size_t)src * DD + c4]);
            float2 f0 = __half22float2(*(__half2*)&hv.x);
            float2 f1 = __half22float2(*(__half2*)&hv.y);
            part.x += w * f0.x; part.y += w * f0.y;
            part.z += w * f1.x; part.w += w * f1.y;
        }
        float scale = g_gw[r] / (denom + 1e-16f);
        acc.x += scale * part.x; acc.y += scale * part.y;
        acc.z += scale * part.z; acc.w += scale * part.w;
    }

    float s = acc.x + acc.y + acc.z + acc.w;
    float q = acc.x * acc.x + acc.y * acc.y + acc.z * acc.z + acc.w * acc.w;
#pragma unroll
    for (int o = 16; o >= 1; o >>= 1) {
        s += __shfl_xor_sync(0xffffffffu, s, o);
        q += __shfl_xor_sync(0xffffffffu, q, o);
    }
    float mu = s * (1.f / DD);
    float var = q * (1.f / DD) - mu * mu;
    float rstd = rsqrtf(var + 1e-5f);
    float4 g = __ldg((const float4*)&gamma[c4]);
    float4 b = __ldg((const float4*)&beta[c4]);
    float4 o4;
    o4.x = (acc.x - mu) * rstd * g.x + b.x;
    o4.y = (acc.y - mu) * rstd * g.y + b.y;
    o4.z = (acc.z - mu) * rstd * g.z + b.z;
    o4.w = (acc.w - mu) * rstd * g.w + b.w;
    *(float4*)&out[(size_t)dst * DD + c4] = o4;
}

// ---------------- launch ------------------------------------------------------------
extern "C" void kernel_launch(void* const* d_in, const int* in_sizes, int n_in,
                              void* d_out, int out_size) {
    const float* x       = (const float*)d_in[0];
    const int*   ei      = (const int*)d_in[1];
    const float* W       = (const float*)d_in[3];
    const float* att_src = (const float*)d_in[4];
    const float* att_dst = (const float*)d_in[5];
    const float* bias    = (const float*)d_in[6];
    const float* gate    = (const float*)d_in[7];
    const float* gamma   = (const float*)d_in[8];
    const float* beta    = (const float*)d_in[9];
    float* out = (float*)d_out;

    static cudaStream_t s2 = nullptr;
    static cudaEvent_t evFork = nullptr, evJoin = nullptr;
    if (s2 == nullptr) {
        cudaStreamCreateWithFlags(&s2, cudaStreamNonBlocking);
        cudaEventCreateWithFlags(&evFork, cudaEventDisableTiming);
        cudaEventCreateWithFlags(&evJoin, cudaEventDisableTiming);
        cudaFuncSetAttribute(k_gemm, cudaFuncAttributeMaxDynamicSharedMemorySize,
                             GEMM_SMEM);
    }

    // fork: CSR-build + prep branch runs concurrently with the GEMM branch
    cudaEventRecord(evFork, 0);
    cudaStreamWaitEvent(s2, evFork, 0);

    // ---- branch B (stream s2): prep + CSR build ----
    k_prep<<<1, DD, 0, s2>>>(gate, bias, out + (out_size - RR));
    k_init<<<(MSEG / 4 + 255) / 256, 256, 0, s2>>>();
    dim3 gh((EE + 511) / 512, RR);
    k_hist<<<gh, 512, 0, s2>>>(ei);
    k_scan_a<<<NSB, 256, 0, s2>>>();
    k_scan_c<<<NSB, 256, 0, s2>>>();
    k_scatter<<<gh, 512, 0, s2>>>(ei);
    cudaEventRecord(evJoin, s2);

    // ---- branch A (default stream): GEMM + fused alpha ----
    dim3 gg((NN + BM - 1) / BM, RR);
    k_gemm<<<gg, 256, GEMM_SMEM>>>(x, W, att_src, att_dst);

    // join, then fused aggregation + residual + LayerNorm
    cudaStreamWaitEvent(0, evJoin, 0);
    k_agg<<<(NN * 32 + 255) / 256, 256>>>(x, gamma, beta, out);
}